// round 15
// baseline (speedup 1.0000x reference)
#include <cuda_runtime.h>

#define B 8
#define A 65536
#define C 80
#define G 16
#define TOPK 50
#define NBINS 8192
#define BSHIFT 17
#define CAND 4096
#define GGRP (A / 32)               // 2048 warp-groups per bg
#define KA_BLOCKS 2048
#define KN_BLOCKS 6144
#define KD_SCAN_BLOCKS 128
#define KD_SP_BLOCKS 256

// ------------------------- static device scratch -------------------------
__device__ unsigned g_hist[(size_t)B * G * NBINS];     // 4.2 MB histograms
__device__ unsigned short g_gmax[(size_t)B * G * GGRP];// 512 KB warp-group max bins+1
__device__ unsigned g_maxiou[B * G];                   // max decoded IoU (bits)
__device__ int      g_ccnt[B * G];                     // candidate counts
__device__ unsigned g_cand[(size_t)B * G * CAND];      // candidate anchor ids
__device__ int      g_nrec;                            // sparse record count
__device__ unsigned g_rec[B * A];                      // sparse records (b<<16 | a)
__device__ double   g_sums[2];                         // [0]=pos, [1]=neg

// ------------------------------ helpers ---------------------------------
// _rn-pinned ops: all IoU computations are bitwise identical across call sites.
struct Corners { float x0, y0, x1, y1, area; };

__device__ __forceinline__ Corners corners_rn(const float4 p) {
    Corners c;
    c.x0 = __fmaf_rn(-0.5f, p.z, p.x);
    c.y0 = __fmaf_rn(-0.5f, p.w, p.y);
    c.x1 = __fmaf_rn( 0.5f, p.z, p.x);
    c.y1 = __fmaf_rn( 0.5f, p.w, p.y);
    c.area = __fmul_rn(p.z, p.w);
    return c;
}

__device__ __forceinline__ float iou_ct(const Corners c, const float4 t, float tA) {
    float iw = fmaxf(__fsub_rn(fminf(c.x1, t.z), fmaxf(c.x0, t.x)), 0.f);
    float ih = fmaxf(__fsub_rn(fminf(c.y1, t.w), fmaxf(c.y0, t.y)), 0.f);
    float inter = __fmul_rn(iw, ih);
    if (inter <= 0.f) return 0.f;
    return __fdividef(inter, __fsub_rn(__fadd_rn(tA, c.area), inter));
}

__device__ __forceinline__ float fiou_rn(const float4 t, float tA,
                                         float bx0, float by0, float bx1, float by1, float bA) {
    float iw = fmaxf(__fsub_rn(fminf(t.z, bx1), fmaxf(t.x, bx0)), 0.f);
    float ih = fmaxf(__fsub_rn(fminf(t.w, by1), fmaxf(t.y, by0)), 0.f);
    float inter = __fmul_rn(iw, ih);
    if (inter <= 0.f) return 0.f;
    return __fdividef(inter, __fsub_rn(__fadd_rn(tA, bA), inter));
}

__device__ __forceinline__ float fastrcp(float s) {
    float r = __uint_as_float(0x7EF311C3u - __float_as_uint(s));
    r = r * (2.f - s * r);
    r = r * (2.f - s * r);
    r = r * (2.f - s * r);
    return r;
}

// sigmoid(x)^2 * softplus(x): 2 MUFU (EX2 + LG2)
__device__ __forceinline__ float negterm(float x) {
    float e = __expf(x);
    float s = 1.f + e;
    float p = e * fastrcp(s);
    return p * p * __logf(s);
}

__device__ __forceinline__ float sl1(float v) {
    float av = fabsf(v);
    return (av < 0.11f) ? 4.5454545454545450f * v * v : av - 0.055f;
}

__device__ __forceinline__ float blockReduceSum(float v) {
    __shared__ float s[32];
    int lane = threadIdx.x & 31, wid = threadIdx.x >> 5;
    #pragma unroll
    for (int o = 16; o; o >>= 1) v += __shfl_down_sync(0xffffffffu, v, o);
    if (lane == 0) s[wid] = v;
    __syncthreads();
    int nw = (blockDim.x + 31) >> 5;
    v = (threadIdx.x < nw) ? s[threadIdx.x] : 0.f;
    if (wid == 0) {
        #pragma unroll
        for (int o = 16; o; o >>= 1) v += __shfl_down_sync(0xffffffffu, v, o);
    }
    return v; // valid in thread 0
}

// ------------------------------ kernels ---------------------------------
__global__ void kI() {
    size_t i = (size_t)blockIdx.x * blockDim.x + threadIdx.x;
    uint4* h4 = (uint4*)g_hist;
    const size_t n4 = (size_t)B * G * NBINS / 4;
    if (i < n4) h4[i] = make_uint4(0u, 0u, 0u, 0u);
    if (i < B * G) { g_maxiou[i] = 0u; g_ccnt[i] = 0; }
    if (i == 0) { g_sums[0] = 0.0; g_sums[1] = 0.0; g_nrec = 0; }
}

// Fused, interleaved: blocks with (blockIdx.x & 3)==0 = per-anchor pass
// (hist + warp-group max + t2 max + sparse records); rest = dense negative loss.
__global__ void kAN(const float4* __restrict__ br, const float4* __restrict__ anc,
                    const float4* __restrict__ tbx, const float4* __restrict__ logits4) {
    if ((blockIdx.x & 3) == 0) {
        int bx = blockIdx.x >> 2;                // 0..KA_BLOCKS-1
        int b = bx >> 8;
        int a = ((bx & 255) << 8) | threadIdx.x;
        __shared__ float4 st[G];
        __shared__ float  sta[G];
        __shared__ unsigned smax[G];
        if (threadIdx.x < G) {
            float4 t = tbx[b * G + threadIdx.x];
            st[threadIdx.x] = t;
            sta[threadIdx.x] = __fmul_rn(__fsub_rn(t.z, t.x), __fsub_rn(t.w, t.y));
            smax[threadIdx.x] = 0u;
        }
        __syncthreads();

        float4 l = br[b * A + a];
        float4 p = anc[a];
        Corners ac = corners_rn(p);
        float dcx = p.x + l.x * 0.1f * p.z;
        float dcy = p.y + l.y * 0.1f * p.w;
        float dw  = p.z * __expf(l.z * 0.2f);
        float dh  = p.w * __expf(l.w * 0.2f);
        float dx0 = dcx - 0.5f * dw, dy0 = dcy - 0.5f * dh;
        float dx1 = dcx + 0.5f * dw, dy1 = dcy + 0.5f * dh;
        float dA  = dw * dh;

        size_t hbase = (size_t)(b * G) * NBINS;
        float dmax = 0.f;
        #pragma unroll
        for (int g = 0; g < G; g++) {
            float4 t = st[g];
            // mqm IoU: histogram + warp-group max summary
            float mi = iou_ct(ac, t, sta[g]);
            unsigned bin1 = 0u;
            if (mi > 0.f) {
                unsigned bin = __float_as_uint(mi) >> BSHIFT;
                bin1 = bin + 1u;
                atomicAdd(&g_hist[hbase + (size_t)g * NBINS + bin], 1u);
            }
            unsigned wmax = __reduce_max_sync(0xffffffffu, bin1);
            if ((threadIdx.x & 31) == 0)
                g_gmax[(size_t)(b * G + g) * GGRP + (a >> 5)] = (unsigned short)wmax;
            // decoded IoU: t2 max
            float di = fiou_rn(t, sta[g], dx0, dy0, dx1, dy1, dA);
            dmax = fmaxf(dmax, di);
            unsigned db = __float_as_uint(di);
            if (db > smax[g]) atomicMax(&smax[g], db);   // read-filtered max
        }
        if (dmax > 0.49f) {                      // margin vs recompute drift
            int pos = atomicAdd(&g_nrec, 1);
            g_rec[pos] = ((unsigned)b << 16) | (unsigned)a;
        }
        __syncthreads();
        if (threadIdx.x < G) atomicMax(&g_maxiou[b * G + threadIdx.x], smax[threadIdx.x]);
    } else {
        const int n4 = B * A * C / 4;
        int bid = blockIdx.x - (blockIdx.x >> 2) - 1;   // 0..KN_BLOCKS-1
        float acc = 0.f;
        for (int i = bid * blockDim.x + threadIdx.x; i < n4; i += KN_BLOCKS * blockDim.x) {
            float4 v = logits4[i];
            acc += negterm(v.x) + negterm(v.y) + negterm(v.z) + negterm(v.w);
        }
        float tot = blockReduceSum(acc);
        if (threadIdx.x == 0) atomicAdd(&g_sums[1], (double)tot);
    }
}

// Fused post-pass:
//  blocks [0,128): per-bg threshold (from histogram) + hierarchical candidate scan
//  blocks [128,384): sparse neg-loss correction
__global__ void kD(const float4* __restrict__ br, const float4* __restrict__ anc,
                   const float4* __restrict__ tbx, const int* __restrict__ lab,
                   const float* __restrict__ logits) {
    if (blockIdx.x < KD_SCAN_BLOCKS) {
        __shared__ unsigned sb[NBINS];
        __shared__ unsigned sp[256];
        __shared__ int stbin;
        int bg = blockIdx.x;
        int tid = threadIdx.x;
        const unsigned* h = g_hist + (size_t)bg * NBINS;
        unsigned acc = 0;
        #pragma unroll 4
        for (int i = 0; i < NBINS / 256; i++) {
            unsigned v = h[tid * (NBINS / 256) + i];
            sb[tid * (NBINS / 256) + i] = v;
            acc += v;
        }
        sp[tid] = acc;
        __syncthreads();
        if (tid == 0) {
            int cum = 0, tb = 0;
            for (int c = 255; c >= 0; c--) {
                if (cum + (int)sp[c] >= TOPK) {
                    int base = c * (NBINS / 256);
                    for (int i = NBINS / 256 - 1; i >= 0; i--) {
                        cum += (int)sb[base + i];
                        if (cum >= TOPK) { tb = base + i; break; }
                    }
                    break;
                }
                cum += (int)sp[c];
            }
            stbin = tb;
        }
        __syncthreads();
        unsigned tb1 = (unsigned)stbin + 1u;
        float thrf = __uint_as_float((unsigned)stbin << BSHIFT);
        float4 t = tbx[bg];
        float tA = __fmul_rn(__fsub_rn(t.z, t.x), __fsub_rn(t.w, t.y));
        const unsigned short* gmx = g_gmax + (size_t)bg * GGRP;
        // 2048 groups / 256 threads = 8 per thread; passing groups are rare
        #pragma unroll
        for (int i = 0; i < GGRP / 256; i++) {
            int grp = i * 256 + tid;
            if ((unsigned)gmx[grp] >= tb1) {     // group provably contains a candidate
                int abase = grp << 5;
                for (int j = 0; j < 32; j++) {
                    int a = abase + j;
                    Corners ac = corners_rn(anc[a]);
                    float mi = iou_ct(ac, t, tA);   // bit-identical to kAN's value
                    if (mi > 0.f && mi >= thrf) {
                        int pos = atomicAdd(&g_ccnt[bg], 1);
                        if (pos < CAND) g_cand[(size_t)bg * CAND + pos] = (unsigned)a;
                    }
                }
            }
        }
    } else {
        __shared__ float4 st[B * G];
        __shared__ float  sta[B * G];
        __shared__ float  sinv[B * G];
        __shared__ int    slbl[B * G];
        __shared__ int    sfirst[B * G];
        if (threadIdx.x < B * G) {
            float4 t = tbx[threadIdx.x];
            st[threadIdx.x] = t;
            sta[threadIdx.x] = __fmul_rn(__fsub_rn(t.z, t.x), __fsub_rn(t.w, t.y));
            slbl[threadIdx.x] = lab[threadIdx.x];
            float m = __uint_as_float(g_maxiou[threadIdx.x]);
            sinv[threadIdx.x] = (m > 0.5f) ? __fdividef(1.f, m - 0.5f) : 0.f;
        }
        __syncthreads();
        if (threadIdx.x < B * G) {
            int b = threadIdx.x >> 4, g = threadIdx.x & 15, f = 1;
            for (int j = 0; j < g; j++) if (slbl[b * G + j] == slbl[threadIdx.x]) f = 0;
            sfirst[threadIdx.x] = f;
        }
        __syncthreads();

        int nrec = g_nrec;
        int bid = blockIdx.x - KD_SCAN_BLOCKS;
        float corr = 0.f;
        for (int i = bid * blockDim.x + threadIdx.x; i < nrec; i += KD_SP_BLOCKS * blockDim.x) {
            unsigned rec = g_rec[i];
            int b = rec >> 16;
            int a = rec & 0xffff;
            float4 l = br[b * A + a];
            float4 p = anc[a];
            float dcx = p.x + l.x * 0.1f * p.z;
            float dcy = p.y + l.y * 0.1f * p.w;
            float dw  = p.z * __expf(l.z * 0.2f);
            float dh  = p.w * __expf(l.w * 0.2f);
            float dx0 = dcx - 0.5f * dw, dy0 = dcy - 0.5f * dh;
            float dx1 = dcx + 0.5f * dw, dy1 = dcy + 0.5f * dh;
            float dA  = dw * dh;
            float obp[G];
            #pragma unroll
            for (int g = 0; g < G; g++) {
                int bg = b * G + g;
                float di = fiou_rn(st[bg], sta[bg], dx0, dy0, dx1, dy1, dA);
                obp[g] = fminf(fmaxf((di - 0.5f) * sinv[bg], 0.f), 1.f);
            }
            #pragma unroll
            for (int g = 0; g < G; g++) {
                int bg = b * G + g;
                if (!sfirst[bg]) continue;
                float bp = obp[g];
                #pragma unroll
                for (int j = g + 1; j < G; j++)
                    if (slbl[b * G + j] == slbl[bg]) bp = fmaxf(bp, obp[j]);
                if (bp > 0.f) {
                    float xl = logits[((size_t)(b * A) + a) * C + slbl[bg]];
                    float pt = negterm(xl);               // cancels dense term exactly
                    float e = __expf(xl);
                    float pp = e * fastrcp(1.f + e);
                    float x = pp * (1.f - bp);
                    float xt = x * x * (-__logf(1.f - x));
                    corr += xt - pt;
                }
            }
        }
        float tot = blockReduceSum(corr);
        if (threadIdx.x == 0 && tot != 0.f) atomicAdd(&g_sums[1], (double)tot);
    }
}

// Exact top-50 select (recompute exact mqm per candidate) + positive bag loss
__global__ void kS(const float4* __restrict__ br, const float4* __restrict__ anc,
                   const float4* __restrict__ tbx, const int* __restrict__ lab,
                   const float* __restrict__ logits) {
    int bg = blockIdx.x;
    int b = bg >> 4, g = bg & 15;
    __shared__ unsigned long long skey[CAND];
    __shared__ unsigned ssel[TOPK];
    __shared__ float swv[TOPK], swl[TOPK];
    __shared__ int scount;
    float4 t = tbx[b * G + g];
    float tA = __fmul_rn(__fsub_rn(t.z, t.x), __fsub_rn(t.w, t.y));
    int cnt = min(g_ccnt[bg], CAND);
    for (int i = threadIdx.x; i < cnt; i += blockDim.x) {
        unsigned a = g_cand[(size_t)bg * CAND + i];
        Corners ac = corners_rn(anc[a]);
        float mi = iou_ct(ac, t, tA);            // bit-identical across kernels
        skey[i] = ((unsigned long long)__float_as_uint(mi) << 32) | (unsigned)(~a);
    }
    if (threadIdx.x == 0) scount = 0;
    __syncthreads();
    for (int i = threadIdx.x; i < cnt; i += blockDim.x) {
        unsigned long long k = skey[i];
        int r = 0;
        for (int j = 0; j < cnt; j++) r += (skey[j] > k);
        if (r < TOPK) {
            int s = atomicAdd(&scount, 1);
            ssel[s] = ~(unsigned)(k & 0xffffffffu);
        }
    }
    __syncthreads();
    int n = scount;
    if (threadIdx.x < n) {
        unsigned a = ssel[threadIdx.x];
        float4 p = anc[a];
        float4 l = br[(size_t)b * A + a];
        int lbl = lab[b * G + g];
        float xl = logits[((size_t)(b * A) + a) * C + lbl];
        float e = __expf(xl);
        float mcp = __fdividef(e, 1.f + e);
        float gx = __fdividef((t.x + t.z) * 0.5f - p.x, 0.1f * p.z);
        float gy = __fdividef((t.y + t.w) * 0.5f - p.y, 0.1f * p.w);
        float gw = __logf(__fdividef(t.z - t.x, p.z)) * 5.0f;
        float gh = __logf(__fdividef(t.w - t.y, p.w)) * 5.0f;
        float reg = 0.75f * (sl1(gx - l.x) + sl1(gy - l.y) + sl1(gw - l.z) + sl1(gh - l.w));
        float mbp = __expf(-reg);
        float li = mcp * mbp;
        float w = __fdividef(1.f, fmaxf(1.f - li, 1e-12f));
        swv[threadIdx.x] = w;
        swl[threadIdx.x] = w * li;
    }
    __syncthreads();
    if (threadIdx.x == 0 && n > 0) {
        float sw = 0.f, sl = 0.f;
        for (int i = 0; i < n; i++) { sw += swv[i]; sl += swl[i]; }
        float bag = __fdividef(sl, sw);
        atomicAdd(&g_sums[0], (double)(-__logf(bag)));
    }
}

__global__ void kF(float* out) {
    out[0] = (float)(g_sums[0] * (0.5 / 128.0));    // ALPHA / (B*G)
    out[1] = (float)(g_sums[1] * (0.5 / 6400.0));   // (1-ALPHA) / (B*G*TOPK)
}

// ------------------------------ launch -----------------------------------
extern "C" void kernel_launch(void* const* d_in, const int* in_sizes, int n_in,
                              void* d_out, int out_size) {
    const float4* br     = (const float4*)d_in[0];   // box_regression (B,A,4)
    const float*  logits = (const float*) d_in[1];   // cls_logits (B,A,C)
    const float4* anc    = (const float4*)d_in[2];   // anchors (A,4)
    const float4* tbx    = (const float4*)d_in[3];   // targets_boxes (B,G,4)
    const int*    lab    = (const int*)   d_in[4];   // labels (B,G)
    float* out = (float*)d_out;

    kI<<<1024, 256>>>();
    kAN<<<KA_BLOCKS + KN_BLOCKS, 256>>>(br, anc, tbx, (const float4*)logits);
    kD<<<KD_SCAN_BLOCKS + KD_SP_BLOCKS, 256>>>(br, anc, tbx, lab, logits);
    kS<<<B * G, 256>>>(br, anc, tbx, lab, logits);
    kF<<<1, 1>>>(out);
}

// round 16
// speedup vs baseline: 1.0994x; 1.0994x over previous
#include <cuda_runtime.h>

#define B 8
#define A 65536
#define C 80
#define G 16
#define TOPK 50
#define NBINS 8192
#define BSHIFT 17
#define CAND 4096
#define KA_BLOCKS 2048
#define KN_BLOCKS 6144
#define KD_CAND_BLOCKS 1024         // 128 bg x 8 chunks
#define KD_SP_BLOCKS 1024

// ------------------------- static device scratch -------------------------
__device__ unsigned g_hist[(size_t)B * G * NBINS];     // 4.2 MB histograms
__device__ unsigned g_maxiou[B * G];                   // max decoded IoU (bits)
__device__ int      g_tbin[B * G];                     // threshold bin
__device__ float    g_invden[B * G];                   // 1/(t2-0.5) or 0
__device__ int      g_ccnt[B * G];                     // candidate counts
__device__ unsigned g_cand[(size_t)B * G * CAND];      // candidate anchor ids
__device__ unsigned short g_mbin[(size_t)B * G * A];   // 16.8 MB mqm bins+1 (0 = no overlap)
__device__ int      g_nrec;                            // sparse record count
__device__ unsigned g_rec[B * A];                      // sparse records (b<<16 | a)
__device__ unsigned g_done;                            // kS completion counter
__device__ double   g_sums[2];                         // [0]=pos, [1]=neg

// ------------------------------ helpers ---------------------------------
// _rn-pinned ops: all IoU computations are bitwise identical across call sites.
struct Corners { float x0, y0, x1, y1, area; };

__device__ __forceinline__ Corners corners_rn(const float4 p) {
    Corners c;
    c.x0 = __fmaf_rn(-0.5f, p.z, p.x);
    c.y0 = __fmaf_rn(-0.5f, p.w, p.y);
    c.x1 = __fmaf_rn( 0.5f, p.z, p.x);
    c.y1 = __fmaf_rn( 0.5f, p.w, p.y);
    c.area = __fmul_rn(p.z, p.w);
    return c;
}

__device__ __forceinline__ float iou_ct(const Corners c, const float4 t, float tA) {
    float iw = fmaxf(__fsub_rn(fminf(c.x1, t.z), fmaxf(c.x0, t.x)), 0.f);
    float ih = fmaxf(__fsub_rn(fminf(c.y1, t.w), fmaxf(c.y0, t.y)), 0.f);
    float inter = __fmul_rn(iw, ih);
    if (inter <= 0.f) return 0.f;
    return __fdividef(inter, __fsub_rn(__fadd_rn(tA, c.area), inter));
}

__device__ __forceinline__ float fiou_rn(const float4 t, float tA,
                                         float bx0, float by0, float bx1, float by1, float bA) {
    float iw = fmaxf(__fsub_rn(fminf(t.z, bx1), fmaxf(t.x, bx0)), 0.f);
    float ih = fmaxf(__fsub_rn(fminf(t.w, by1), fmaxf(t.y, by0)), 0.f);
    float inter = __fmul_rn(iw, ih);
    if (inter <= 0.f) return 0.f;
    return __fdividef(inter, __fsub_rn(__fadd_rn(tA, bA), inter));
}

__device__ __forceinline__ float fastrcp(float s) {
    float r = __uint_as_float(0x7EF311C3u - __float_as_uint(s));
    r = r * (2.f - s * r);
    r = r * (2.f - s * r);
    r = r * (2.f - s * r);
    return r;
}

// sigmoid(x)^2 * softplus(x): 2 MUFU (EX2 + LG2)
__device__ __forceinline__ float negterm(float x) {
    float e = __expf(x);
    float s = 1.f + e;
    float p = e * fastrcp(s);
    return p * p * __logf(s);
}

__device__ __forceinline__ float sl1(float v) {
    float av = fabsf(v);
    return (av < 0.11f) ? 4.5454545454545450f * v * v : av - 0.055f;
}

__device__ __forceinline__ float blockReduceSum(float v) {
    __shared__ float s[32];
    int lane = threadIdx.x & 31, wid = threadIdx.x >> 5;
    #pragma unroll
    for (int o = 16; o; o >>= 1) v += __shfl_down_sync(0xffffffffu, v, o);
    if (lane == 0) s[wid] = v;
    __syncthreads();
    int nw = (blockDim.x + 31) >> 5;
    v = (threadIdx.x < nw) ? s[threadIdx.x] : 0.f;
    if (wid == 0) {
        #pragma unroll
        for (int o = 16; o; o >>= 1) v += __shfl_down_sync(0xffffffffu, v, o);
    }
    return v; // valid in thread 0
}

// ------------------------------ kernels ---------------------------------
__global__ void kI() {
    size_t i = (size_t)blockIdx.x * blockDim.x + threadIdx.x;
    uint4* h4 = (uint4*)g_hist;
    const size_t n4 = (size_t)B * G * NBINS / 4;
    if (i < n4) h4[i] = make_uint4(0u, 0u, 0u, 0u);
    if (i < B * G) { g_maxiou[i] = 0u; g_ccnt[i] = 0; }
    if (i == 0) { g_sums[0] = 0.0; g_sums[1] = 0.0; g_nrec = 0; g_done = 0u; }
}

// Fused: blocks [0,KA_BLOCKS) = per-anchor pass (hist + bin store + t2 max +
//        sparse records); rest = dense negative loss over logits.
__global__ void kAN(const float4* __restrict__ br, const float4* __restrict__ anc,
                    const float4* __restrict__ tbx, const float4* __restrict__ logits4) {
    if (blockIdx.x < KA_BLOCKS) {
        int b = blockIdx.x >> 8;
        int a = ((blockIdx.x & 255) << 8) | threadIdx.x;
        __shared__ float4 st[G];
        __shared__ float  sta[G];
        __shared__ unsigned smax[G];
        if (threadIdx.x < G) {
            float4 t = tbx[b * G + threadIdx.x];
            st[threadIdx.x] = t;
            sta[threadIdx.x] = __fmul_rn(__fsub_rn(t.z, t.x), __fsub_rn(t.w, t.y));
            smax[threadIdx.x] = 0u;
        }
        __syncthreads();

        float4 l = br[b * A + a];
        float4 p = anc[a];
        Corners ac = corners_rn(p);
        float dcx = p.x + l.x * 0.1f * p.z;
        float dcy = p.y + l.y * 0.1f * p.w;
        float dw  = p.z * __expf(l.z * 0.2f);
        float dh  = p.w * __expf(l.w * 0.2f);
        float dx0 = dcx - 0.5f * dw, dy0 = dcy - 0.5f * dh;
        float dx1 = dcx + 0.5f * dw, dy1 = dcy + 0.5f * dh;
        float dA  = dw * dh;

        size_t hbase = (size_t)(b * G) * NBINS;
        float dmax = 0.f;
        #pragma unroll
        for (int g = 0; g < G; g++) {
            float4 t = st[g];
            // mqm IoU: histogram + persisted bin (the ONLY full-grid mqm compute)
            float mi = iou_ct(ac, t, sta[g]);
            unsigned bin1 = 0u;
            if (mi > 0.f) {
                unsigned bin = __float_as_uint(mi) >> BSHIFT;
                bin1 = bin + 1u;
                atomicAdd(&g_hist[hbase + (size_t)g * NBINS + bin], 1u);
            }
            g_mbin[(size_t)(b * G + g) * A + a] = (unsigned short)bin1;
            // decoded IoU: t2 max
            float di = fiou_rn(t, sta[g], dx0, dy0, dx1, dy1, dA);
            dmax = fmaxf(dmax, di);
            unsigned db = __float_as_uint(di);
            if (db > smax[g]) atomicMax(&smax[g], db);   // read-filtered max
        }
        if (dmax > 0.49f) {                      // margin vs recompute drift
            int pos = atomicAdd(&g_nrec, 1);
            g_rec[pos] = ((unsigned)b << 16) | (unsigned)a;
        }
        __syncthreads();
        if (threadIdx.x < G) atomicMax(&g_maxiou[b * G + threadIdx.x], smax[threadIdx.x]);
    } else {
        const int n4 = B * A * C / 4;
        int bid = blockIdx.x - KA_BLOCKS;
        float acc = 0.f;
        for (int i = bid * blockDim.x + threadIdx.x; i < n4; i += KN_BLOCKS * blockDim.x) {
            float4 v = logits4[i];
            acc += negterm(v.x) + negterm(v.y) + negterm(v.z) + negterm(v.w);
        }
        float tot = blockReduceSum(acc);
        if (threadIdx.x == 0) atomicAdd(&g_sums[1], (double)tot);
    }
}

// Threshold per (b,g): largest suffix bin with count >= TOPK; invden
__global__ void kT() {
    int bg = blockIdx.x;
    const unsigned* h = g_hist + (size_t)bg * NBINS;
    __shared__ unsigned sb[NBINS];
    __shared__ unsigned sp[256];
    int t = threadIdx.x;
    unsigned acc = 0;
    #pragma unroll 4
    for (int i = 0; i < NBINS / 256; i++) {
        unsigned v = h[t * (NBINS / 256) + i];
        sb[t * (NBINS / 256) + i] = v;
        acc += v;
    }
    sp[t] = acc;
    __syncthreads();
    if (t == 0) {
        int cum = 0, tb = 0;
        for (int c = 255; c >= 0; c--) {
            if (cum + (int)sp[c] >= TOPK) {
                int base = c * (NBINS / 256);
                for (int i = NBINS / 256 - 1; i >= 0; i--) {
                    cum += (int)sb[base + i];
                    if (cum >= TOPK) { tb = base + i; break; }
                }
                break;
            }
            cum += (int)sp[c];
        }
        g_tbin[bg] = tb;
        float m = __uint_as_float(g_maxiou[bg]);
        g_invden[bg] = (m > 0.5f) ? __fdividef(1.f, m - 0.5f) : 0.f;
    }
}

// Fused post-threshold:
//  blocks [0,KD_CAND_BLOCKS): pure-bandwidth candidate scan of stored bins
//   (block = bg x eighth; each thread: 4 uint4 loads = 32 packed u16 bins)
//  rest: sparse neg-loss correction (1024 blocks for latency hiding).
__global__ void kD(const float4* __restrict__ br, const float4* __restrict__ anc,
                   const float4* __restrict__ tbx, const int* __restrict__ lab,
                   const float* __restrict__ logits) {
    if (blockIdx.x < KD_CAND_BLOCKS) {
        int bg = blockIdx.x >> 3;
        int chunk = blockIdx.x & 7;
        unsigned tb1 = (unsigned)g_tbin[bg] + 1u;  // stored bins are bin+1
        const uint4* mb = (const uint4*)(g_mbin + (size_t)bg * A + chunk * (A / 8));
        // A/8 = 8192 anchors per chunk; 8 anchors per uint4 -> 1024 uint4 / 256 thr = 4 iters
        #pragma unroll
        for (int i = 0; i < 4; i++) {
            int idx = i * 256 + threadIdx.x;
            uint4 v = mb[idx];
            int abase = chunk * (A / 8) + idx * 8;
            unsigned w[4] = { v.x, v.y, v.z, v.w };
            #pragma unroll
            for (int j = 0; j < 4; j++) {
                unsigned lo = w[j] & 0xffffu, hi = w[j] >> 16;
                if (lo >= tb1) {
                    int pos = atomicAdd(&g_ccnt[bg], 1);
                    if (pos < CAND) g_cand[(size_t)bg * CAND + pos] = (unsigned)(abase + 2 * j);
                }
                if (hi >= tb1) {
                    int pos = atomicAdd(&g_ccnt[bg], 1);
                    if (pos < CAND) g_cand[(size_t)bg * CAND + pos] = (unsigned)(abase + 2 * j + 1);
                }
            }
        }
    } else {
        __shared__ float4 st[B * G];
        __shared__ float  sta[B * G];
        __shared__ float  sinv[B * G];
        __shared__ int    slbl[B * G];
        __shared__ int    sfirst[B * G];
        if (threadIdx.x < B * G) {
            float4 t = tbx[threadIdx.x];
            st[threadIdx.x] = t;
            sta[threadIdx.x] = __fmul_rn(__fsub_rn(t.z, t.x), __fsub_rn(t.w, t.y));
            sinv[threadIdx.x] = g_invden[threadIdx.x];
            slbl[threadIdx.x] = lab[threadIdx.x];
        }
        __syncthreads();
        if (threadIdx.x < B * G) {
            int b = threadIdx.x >> 4, g = threadIdx.x & 15, f = 1;
            for (int j = 0; j < g; j++) if (slbl[b * G + j] == slbl[threadIdx.x]) f = 0;
            sfirst[threadIdx.x] = f;
        }
        __syncthreads();

        int nrec = g_nrec;
        int bid = blockIdx.x - KD_CAND_BLOCKS;
        float corr = 0.f;
        for (int i = bid * blockDim.x + threadIdx.x; i < nrec; i += KD_SP_BLOCKS * blockDim.x) {
            unsigned rec = g_rec[i];
            int b = rec >> 16;
            int a = rec & 0xffff;
            float4 l = br[b * A + a];
            float4 p = anc[a];
            float dcx = p.x + l.x * 0.1f * p.z;
            float dcy = p.y + l.y * 0.1f * p.w;
            float dw  = p.z * __expf(l.z * 0.2f);
            float dh  = p.w * __expf(l.w * 0.2f);
            float dx0 = dcx - 0.5f * dw, dy0 = dcy - 0.5f * dh;
            float dx1 = dcx + 0.5f * dw, dy1 = dcy + 0.5f * dh;
            float dA  = dw * dh;
            float obp[G];
            #pragma unroll
            for (int g = 0; g < G; g++) {
                int bg = b * G + g;
                float di = fiou_rn(st[bg], sta[bg], dx0, dy0, dx1, dy1, dA);
                obp[g] = fminf(fmaxf((di - 0.5f) * sinv[bg], 0.f), 1.f);
            }
            #pragma unroll
            for (int g = 0; g < G; g++) {
                int bg = b * G + g;
                if (!sfirst[bg]) continue;
                float bp = obp[g];
                #pragma unroll
                for (int j = g + 1; j < G; j++)
                    if (slbl[b * G + j] == slbl[bg]) bp = fmaxf(bp, obp[j]);
                if (bp > 0.f) {
                    float xl = logits[((size_t)(b * A) + a) * C + slbl[bg]];
                    float pt = negterm(xl);               // cancels dense term exactly
                    float e = __expf(xl);
                    float pp = e * fastrcp(1.f + e);
                    float x = pp * (1.f - bp);
                    float xt = x * x * (-__logf(1.f - x));
                    corr += xt - pt;
                }
            }
        }
        float tot = blockReduceSum(corr);
        if (threadIdx.x == 0 && tot != 0.f) atomicAdd(&g_sums[1], (double)tot);
    }
}

// Exact top-50 select (recompute exact mqm per candidate) + positive bag loss.
// Last-finishing block also writes the final output (all sums complete by then:
// kD precedes kS in stream order; kS blocks publish via threadfence + counter).
__global__ void kS(const float4* __restrict__ br, const float4* __restrict__ anc,
                   const float4* __restrict__ tbx, const int* __restrict__ lab,
                   const float* __restrict__ logits, float* __restrict__ out) {
    int bg = blockIdx.x;
    int b = bg >> 4, g = bg & 15;
    __shared__ unsigned long long skey[CAND];
    __shared__ unsigned ssel[TOPK];
    __shared__ float swv[TOPK], swl[TOPK];
    __shared__ int scount;
    float4 t = tbx[b * G + g];
    float tA = __fmul_rn(__fsub_rn(t.z, t.x), __fsub_rn(t.w, t.y));
    int cnt = min(g_ccnt[bg], CAND);
    for (int i = threadIdx.x; i < cnt; i += blockDim.x) {
        unsigned a = g_cand[(size_t)bg * CAND + i];
        Corners ac = corners_rn(anc[a]);
        float mi = iou_ct(ac, t, tA);            // bit-identical across kernels
        skey[i] = ((unsigned long long)__float_as_uint(mi) << 32) | (unsigned)(~a);
    }
    if (threadIdx.x == 0) scount = 0;
    __syncthreads();
    for (int i = threadIdx.x; i < cnt; i += blockDim.x) {
        unsigned long long k = skey[i];
        int r = 0;
        for (int j = 0; j < cnt; j++) r += (skey[j] > k);
        if (r < TOPK) {
            int s = atomicAdd(&scount, 1);
            ssel[s] = ~(unsigned)(k & 0xffffffffu);
        }
    }
    __syncthreads();
    int n = scount;
    if (threadIdx.x < n) {
        unsigned a = ssel[threadIdx.x];
        float4 p = anc[a];
        float4 l = br[(size_t)b * A + a];
        int lbl = lab[b * G + g];
        float xl = logits[((size_t)(b * A) + a) * C + lbl];
        float e = __expf(xl);
        float mcp = __fdividef(e, 1.f + e);
        float gx = __fdividef((t.x + t.z) * 0.5f - p.x, 0.1f * p.z);
        float gy = __fdividef((t.y + t.w) * 0.5f - p.y, 0.1f * p.w);
        float gw = __logf(__fdividef(t.z - t.x, p.z)) * 5.0f;
        float gh = __logf(__fdividef(t.w - t.y, p.w)) * 5.0f;
        float reg = 0.75f * (sl1(gx - l.x) + sl1(gy - l.y) + sl1(gw - l.z) + sl1(gh - l.w));
        float mbp = __expf(-reg);
        float li = mcp * mbp;
        float w = __fdividef(1.f, fmaxf(1.f - li, 1e-12f));
        swv[threadIdx.x] = w;
        swl[threadIdx.x] = w * li;
    }
    __syncthreads();
    if (threadIdx.x == 0) {
        if (n > 0) {
            float sw = 0.f, sl = 0.f;
            for (int i = 0; i < n; i++) { sw += swv[i]; sl += swl[i]; }
            float bag = __fdividef(sl, sw);
            atomicAdd(&g_sums[0], (double)(-__logf(bag)));
        }
        __threadfence();
        unsigned done = atomicAdd(&g_done, 1u);
        if (done == (unsigned)(B * G - 1)) {     // last block: all sums final
            double s0 = atomicAdd(&g_sums[0], 0.0);
            double s1 = atomicAdd(&g_sums[1], 0.0);
            out[0] = (float)(s0 * (0.5 / 128.0));    // ALPHA / (B*G)
            out[1] = (float)(s1 * (0.5 / 6400.0));   // (1-ALPHA) / (B*G*TOPK)
        }
    }
}

// ------------------------------ launch -----------------------------------
extern "C" void kernel_launch(void* const* d_in, const int* in_sizes, int n_in,
                              void* d_out, int out_size) {
    const float4* br     = (const float4*)d_in[0];   // box_regression (B,A,4)
    const float*  logits = (const float*) d_in[1];   // cls_logits (B,A,C)
    const float4* anc    = (const float4*)d_in[2];   // anchors (A,4)
    const float4* tbx    = (const float4*)d_in[3];   // targets_boxes (B,G,4)
    const int*    lab    = (const int*)   d_in[4];   // labels (B,G)
    float* out = (float*)d_out;

    kI<<<1024, 256>>>();
    kAN<<<KA_BLOCKS + KN_BLOCKS, 256>>>(br, anc, tbx, (const float4*)logits);
    kT<<<B * G, 256>>>();
    kD<<<KD_CAND_BLOCKS + KD_SP_BLOCKS, 256>>>(br, anc, tbx, lab, logits);
    kS<<<B * G, 256>>>(br, anc, tbx, lab, logits, out);
}

// round 17
// speedup vs baseline: 1.1522x; 1.0480x over previous
#include <cuda_runtime.h>

#define B 8
#define A 65536
#define C 80
#define G 16
#define TOPK 50
#define NBINS 8192
#define BSHIFT 17
#define CAND 4096
#define KA_BLOCKS 2048
#define KN_BLOCKS 6144
#define KD_SCAN_BLOCKS 256          // B x 32 sub-chunks
#define KD_SP_BLOCKS 256

// ------------------------- static device scratch -------------------------
__device__ unsigned g_hist[(size_t)B * G * NBINS];     // 4.2 MB (self-cleaned in kT)
__device__ unsigned g_maxiou[B * G];                   // max decoded IoU (bits)
__device__ int      g_tbin[B * G];                     // threshold bin
__device__ float    g_invden[B * G];                   // 1/(t2-0.5) or 0
__device__ int      g_ccnt[B * G];                     // candidate counts
__device__ unsigned g_cand[(size_t)B * G * CAND];      // candidate anchor ids
__device__ unsigned short g_mbin[(size_t)B * A * G];   // 16.8 MB bins+1, [b][a][g] packed
__device__ int      g_nrec;                            // sparse record count
__device__ unsigned g_rec[B * A];                      // sparse records (b<<16 | a)
__device__ unsigned g_done;                            // kS completion counter
__device__ double   g_sums[2];                         // [0]=pos, [1]=neg

// ------------------------------ helpers ---------------------------------
// _rn-pinned ops: all IoU computations are bitwise identical across call sites.
struct Corners { float x0, y0, x1, y1, area; };

__device__ __forceinline__ Corners corners_rn(const float4 p) {
    Corners c;
    c.x0 = __fmaf_rn(-0.5f, p.z, p.x);
    c.y0 = __fmaf_rn(-0.5f, p.w, p.y);
    c.x1 = __fmaf_rn( 0.5f, p.z, p.x);
    c.y1 = __fmaf_rn( 0.5f, p.w, p.y);
    c.area = __fmul_rn(p.z, p.w);
    return c;
}

__device__ __forceinline__ float iou_ct(const Corners c, const float4 t, float tA) {
    float iw = fmaxf(__fsub_rn(fminf(c.x1, t.z), fmaxf(c.x0, t.x)), 0.f);
    float ih = fmaxf(__fsub_rn(fminf(c.y1, t.w), fmaxf(c.y0, t.y)), 0.f);
    float inter = __fmul_rn(iw, ih);
    if (inter <= 0.f) return 0.f;
    return __fdividef(inter, __fsub_rn(__fadd_rn(tA, c.area), inter));
}

__device__ __forceinline__ float fiou_rn(const float4 t, float tA,
                                         float bx0, float by0, float bx1, float by1, float bA) {
    float iw = fmaxf(__fsub_rn(fminf(t.z, bx1), fmaxf(t.x, bx0)), 0.f);
    float ih = fmaxf(__fsub_rn(fminf(t.w, by1), fmaxf(t.y, by0)), 0.f);
    float inter = __fmul_rn(iw, ih);
    if (inter <= 0.f) return 0.f;
    return __fdividef(inter, __fsub_rn(__fadd_rn(tA, bA), inter));
}

// magic rcp + 2 Newton: rel err ~1e-6 (sum of positive terms => error ~1e-6 << 1e-3)
__device__ __forceinline__ float fastrcp(float s) {
    float r = __uint_as_float(0x7EF311C3u - __float_as_uint(s));
    r = r * (2.f - s * r);
    r = r * (2.f - s * r);
    return r;
}

// sigmoid(x)^2 * softplus(x): 2 MUFU (EX2 + LG2)
__device__ __forceinline__ float negterm(float x) {
    float e = __expf(x);
    float s = 1.f + e;
    float p = e * fastrcp(s);
    return p * p * __logf(s);
}

__device__ __forceinline__ float sl1(float v) {
    float av = fabsf(v);
    return (av < 0.11f) ? 4.5454545454545450f * v * v : av - 0.055f;
}

__device__ __forceinline__ float blockReduceSum(float v) {
    __shared__ float s[32];
    int lane = threadIdx.x & 31, wid = threadIdx.x >> 5;
    #pragma unroll
    for (int o = 16; o; o >>= 1) v += __shfl_down_sync(0xffffffffu, v, o);
    if (lane == 0) s[wid] = v;
    __syncthreads();
    int nw = (blockDim.x + 31) >> 5;
    v = (threadIdx.x < nw) ? s[threadIdx.x] : 0.f;
    if (wid == 0) {
        #pragma unroll
        for (int o = 16; o; o >>= 1) v += __shfl_down_sync(0xffffffffu, v, o);
    }
    return v; // valid in thread 0
}

// ------------------------------ kernels ---------------------------------
// Small-state init only; g_hist is zero on first run (CUDA zero-init) and
// self-cleaned by kT each iteration thereafter.
__global__ void kI() {
    int i = threadIdx.x;
    if (i < B * G) { g_maxiou[i] = 0u; g_ccnt[i] = 0; }
    if (i == 0) { g_sums[0] = 0.0; g_sums[1] = 0.0; g_nrec = 0; g_done = 0u; }
}

// Fused: blocks [0,KA_BLOCKS) = per-anchor pass (hist + packed bin store +
//        t2 max + sparse records); rest = dense negative loss over logits.
__global__ void kAN(const float4* __restrict__ br, const float4* __restrict__ anc,
                    const float4* __restrict__ tbx, const float4* __restrict__ logits4) {
    if (blockIdx.x < KA_BLOCKS) {
        int b = blockIdx.x >> 8;
        int a = ((blockIdx.x & 255) << 8) | threadIdx.x;
        __shared__ float4 st[G];
        __shared__ float  sta[G];
        __shared__ unsigned smax[G];
        if (threadIdx.x < G) {
            float4 t = tbx[b * G + threadIdx.x];
            st[threadIdx.x] = t;
            sta[threadIdx.x] = __fmul_rn(__fsub_rn(t.z, t.x), __fsub_rn(t.w, t.y));
            smax[threadIdx.x] = 0u;
        }
        __syncthreads();

        float4 l = br[b * A + a];
        float4 p = anc[a];
        Corners ac = corners_rn(p);
        float dcx = p.x + l.x * 0.1f * p.z;
        float dcy = p.y + l.y * 0.1f * p.w;
        float dw  = p.z * __expf(l.z * 0.2f);
        float dh  = p.w * __expf(l.w * 0.2f);
        float dx0 = dcx - 0.5f * dw, dy0 = dcy - 0.5f * dh;
        float dx1 = dcx + 0.5f * dw, dy1 = dcy + 0.5f * dh;
        float dA  = dw * dh;

        size_t hbase = (size_t)(b * G) * NBINS;
        float dmax = 0.f;
        unsigned bins[G];
        #pragma unroll
        for (int g = 0; g < G; g++) {
            float4 t = st[g];
            // mqm IoU: histogram + register-held bin (packed store below)
            float mi = iou_ct(ac, t, sta[g]);
            unsigned bin1 = 0u;
            if (mi > 0.f) {
                unsigned bin = __float_as_uint(mi) >> BSHIFT;
                bin1 = bin + 1u;
                atomicAdd(&g_hist[hbase + (size_t)g * NBINS + bin], 1u);
            }
            bins[g] = bin1;
            // decoded IoU: t2 max
            float di = fiou_rn(t, sta[g], dx0, dy0, dx1, dy1, dA);
            dmax = fmaxf(dmax, di);
            unsigned db = __float_as_uint(di);
            if (db > smax[g]) atomicMax(&smax[g], db);   // read-filtered max
        }
        // pack 16 u16 bins -> 2 x STG.128, layout [b][a][g]
        {
            uint4* dst = (uint4*)(g_mbin + ((size_t)b * A + a) * G);
            uint4 v0, v1;
            v0.x = bins[0]  | (bins[1]  << 16);
            v0.y = bins[2]  | (bins[3]  << 16);
            v0.z = bins[4]  | (bins[5]  << 16);
            v0.w = bins[6]  | (bins[7]  << 16);
            v1.x = bins[8]  | (bins[9]  << 16);
            v1.y = bins[10] | (bins[11] << 16);
            v1.z = bins[12] | (bins[13] << 16);
            v1.w = bins[14] | (bins[15] << 16);
            dst[0] = v0;
            dst[1] = v1;
        }
        if (dmax > 0.49f) {                      // margin vs recompute drift
            int pos = atomicAdd(&g_nrec, 1);
            g_rec[pos] = ((unsigned)b << 16) | (unsigned)a;
        }
        __syncthreads();
        if (threadIdx.x < G) atomicMax(&g_maxiou[b * G + threadIdx.x], smax[threadIdx.x]);
    } else {
        const int n4 = B * A * C / 4;
        int bid = blockIdx.x - KA_BLOCKS;
        float acc = 0.f;
        for (int i = bid * blockDim.x + threadIdx.x; i < n4; i += KN_BLOCKS * blockDim.x) {
            float4 v = logits4[i];
            acc += negterm(v.x) + negterm(v.y) + negterm(v.z) + negterm(v.w);
        }
        float tot = blockReduceSum(acc);
        if (threadIdx.x == 0) atomicAdd(&g_sums[1], (double)tot);
    }
}

// Threshold per (b,g): largest suffix bin with count >= TOPK; invden.
// Also self-cleans its histogram slice for the next graph replay.
__global__ void kT() {
    int bg = blockIdx.x;
    unsigned* h = g_hist + (size_t)bg * NBINS;
    __shared__ unsigned sb[NBINS];
    __shared__ unsigned sp[256];
    int t = threadIdx.x;
    unsigned acc = 0;
    #pragma unroll 4
    for (int i = 0; i < NBINS / 256; i++) {
        unsigned v = h[t * (NBINS / 256) + i];
        sb[t * (NBINS / 256) + i] = v;
        acc += v;
    }
    sp[t] = acc;
    __syncthreads();
    // zero the slice for next iteration (smem copy already taken)
    {
        uint4* h4 = (uint4*)h;
        #pragma unroll
        for (int i = 0; i < NBINS / 4 / 256; i++)
            h4[i * 256 + t] = make_uint4(0u, 0u, 0u, 0u);
    }
    if (t == 0) {
        int cum = 0, tb = 0;
        for (int c = 255; c >= 0; c--) {
            if (cum + (int)sp[c] >= TOPK) {
                int base = c * (NBINS / 256);
                for (int i = NBINS / 256 - 1; i >= 0; i--) {
                    cum += (int)sb[base + i];
                    if (cum >= TOPK) { tb = base + i; break; }
                }
                break;
            }
            cum += (int)sp[c];
        }
        g_tbin[bg] = tb;
        float m = __uint_as_float(g_maxiou[bg]);
        g_invden[bg] = (m > 0.5f) ? __fdividef(1.f, m - 0.5f) : 0.f;
    }
}

// Fused post-threshold:
//  blocks [0,KD_SCAN_BLOCKS): candidate scan of packed bins, block = (b, 1/32 chunk)
//  rest: sparse neg-loss correction.
__global__ void kD(const float4* __restrict__ br, const float4* __restrict__ anc,
                   const float4* __restrict__ tbx, const int* __restrict__ lab,
                   const float* __restrict__ logits) {
    if (blockIdx.x < KD_SCAN_BLOCKS) {
        int b = blockIdx.x >> 5;
        int sub = blockIdx.x & 31;
        __shared__ unsigned stb1[G];
        if (threadIdx.x < G) stb1[threadIdx.x] = (unsigned)g_tbin[b * G + threadIdx.x] + 1u;
        __syncthreads();
        // image b: A anchors x 32B = 131072 uint4; this block: 4096 of them
        const uint4* mb = (const uint4*)(g_mbin + (size_t)b * A * G);
        #pragma unroll
        for (int it = 0; it < 16; it++) {
            int idx = sub * 4096 + it * 256 + threadIdx.x;
            uint4 v = mb[idx];
            int anchor = idx >> 1;
            int gbase = (idx & 1) << 3;       // 0 or 8
            unsigned w[4] = { v.x, v.y, v.z, v.w };
            #pragma unroll
            for (int j = 0; j < 4; j++) {
                int g0 = gbase + 2 * j;
                unsigned lo = w[j] & 0xffffu, hi = w[j] >> 16;
                if (lo >= stb1[g0]) {
                    int bg = b * G + g0;
                    int pos = atomicAdd(&g_ccnt[bg], 1);
                    if (pos < CAND) g_cand[(size_t)bg * CAND + pos] = (unsigned)anchor;
                }
                if (hi >= stb1[g0 + 1]) {
                    int bg = b * G + g0 + 1;
                    int pos = atomicAdd(&g_ccnt[bg], 1);
                    if (pos < CAND) g_cand[(size_t)bg * CAND + pos] = (unsigned)anchor;
                }
            }
        }
    } else {
        __shared__ float4 st[B * G];
        __shared__ float  sta[B * G];
        __shared__ float  sinv[B * G];
        __shared__ int    slbl[B * G];
        __shared__ int    sfirst[B * G];
        if (threadIdx.x < B * G) {
            float4 t = tbx[threadIdx.x];
            st[threadIdx.x] = t;
            sta[threadIdx.x] = __fmul_rn(__fsub_rn(t.z, t.x), __fsub_rn(t.w, t.y));
            sinv[threadIdx.x] = g_invden[threadIdx.x];
            slbl[threadIdx.x] = lab[threadIdx.x];
        }
        __syncthreads();
        if (threadIdx.x < B * G) {
            int b = threadIdx.x >> 4, g = threadIdx.x & 15, f = 1;
            for (int j = 0; j < g; j++) if (slbl[b * G + j] == slbl[threadIdx.x]) f = 0;
            sfirst[threadIdx.x] = f;
        }
        __syncthreads();

        int nrec = g_nrec;
        int bid = blockIdx.x - KD_SCAN_BLOCKS;
        float corr = 0.f;
        for (int i = bid * blockDim.x + threadIdx.x; i < nrec; i += KD_SP_BLOCKS * blockDim.x) {
            unsigned rec = g_rec[i];
            int b = rec >> 16;
            int a = rec & 0xffff;
            float4 l = br[b * A + a];
            float4 p = anc[a];
            float dcx = p.x + l.x * 0.1f * p.z;
            float dcy = p.y + l.y * 0.1f * p.w;
            float dw  = p.z * __expf(l.z * 0.2f);
            float dh  = p.w * __expf(l.w * 0.2f);
            float dx0 = dcx - 0.5f * dw, dy0 = dcy - 0.5f * dh;
            float dx1 = dcx + 0.5f * dw, dy1 = dcy + 0.5f * dh;
            float dA  = dw * dh;
            float obp[G];
            #pragma unroll
            for (int g = 0; g < G; g++) {
                int bg = b * G + g;
                float di = fiou_rn(st[bg], sta[bg], dx0, dy0, dx1, dy1, dA);
                obp[g] = fminf(fmaxf((di - 0.5f) * sinv[bg], 0.f), 1.f);
            }
            #pragma unroll
            for (int g = 0; g < G; g++) {
                int bg = b * G + g;
                if (!sfirst[bg]) continue;
                float bp = obp[g];
                #pragma unroll
                for (int j = g + 1; j < G; j++)
                    if (slbl[b * G + j] == slbl[bg]) bp = fmaxf(bp, obp[j]);
                if (bp > 0.f) {
                    float xl = logits[((size_t)(b * A) + a) * C + slbl[bg]];
                    float pt = negterm(xl);               // cancels dense term exactly
                    float e = __expf(xl);
                    float pp = e * fastrcp(1.f + e);
                    float x = pp * (1.f - bp);
                    float xt = x * x * (-__logf(1.f - x));
                    corr += xt - pt;
                }
            }
        }
        float tot = blockReduceSum(corr);
        if (threadIdx.x == 0 && tot != 0.f) atomicAdd(&g_sums[1], (double)tot);
    }
}

// Exact top-50 select (recompute exact mqm per candidate) + positive bag loss.
// Last-finishing block writes the final output (kD precedes kS in stream order).
__global__ void kS(const float4* __restrict__ br, const float4* __restrict__ anc,
                   const float4* __restrict__ tbx, const int* __restrict__ lab,
                   const float* __restrict__ logits, float* __restrict__ out) {
    int bg = blockIdx.x;
    int b = bg >> 4, g = bg & 15;
    __shared__ unsigned long long skey[CAND];
    __shared__ unsigned ssel[TOPK];
    __shared__ float swv[TOPK], swl[TOPK];
    __shared__ int scount;
    float4 t = tbx[b * G + g];
    float tA = __fmul_rn(__fsub_rn(t.z, t.x), __fsub_rn(t.w, t.y));
    int cnt = min(g_ccnt[bg], CAND);
    for (int i = threadIdx.x; i < cnt; i += blockDim.x) {
        unsigned a = g_cand[(size_t)bg * CAND + i];
        Corners ac = corners_rn(anc[a]);
        float mi = iou_ct(ac, t, tA);            // bit-identical across kernels
        skey[i] = ((unsigned long long)__float_as_uint(mi) << 32) | (unsigned)(~a);
    }
    if (threadIdx.x == 0) scount = 0;
    __syncthreads();
    for (int i = threadIdx.x; i < cnt; i += blockDim.x) {
        unsigned long long k = skey[i];
        int r = 0;
        for (int j = 0; j < cnt; j++) r += (skey[j] > k);
        if (r < TOPK) {
            int s = atomicAdd(&scount, 1);
            ssel[s] = ~(unsigned)(k & 0xffffffffu);
        }
    }
    __syncthreads();
    int n = scount;
    if (threadIdx.x < n) {
        unsigned a = ssel[threadIdx.x];
        float4 p = anc[a];
        float4 l = br[(size_t)b * A + a];
        int lbl = lab[b * G + g];
        float xl = logits[((size_t)(b * A) + a) * C + lbl];
        float e = __expf(xl);
        float mcp = __fdividef(e, 1.f + e);
        float gx = __fdividef((t.x + t.z) * 0.5f - p.x, 0.1f * p.z);
        float gy = __fdividef((t.y + t.w) * 0.5f - p.y, 0.1f * p.w);
        float gw = __logf(__fdividef(t.z - t.x, p.z)) * 5.0f;
        float gh = __logf(__fdividef(t.w - t.y, p.w)) * 5.0f;
        float reg = 0.75f * (sl1(gx - l.x) + sl1(gy - l.y) + sl1(gw - l.z) + sl1(gh - l.w));
        float mbp = __expf(-reg);
        float li = mcp * mbp;
        float w = __fdividef(1.f, fmaxf(1.f - li, 1e-12f));
        swv[threadIdx.x] = w;
        swl[threadIdx.x] = w * li;
    }
    __syncthreads();
    if (threadIdx.x == 0) {
        if (n > 0) {
            float sw = 0.f, sl = 0.f;
            for (int i = 0; i < n; i++) { sw += swv[i]; sl += swl[i]; }
            float bag = __fdividef(sl, sw);
            atomicAdd(&g_sums[0], (double)(-__logf(bag)));
        }
        __threadfence();
        unsigned done = atomicAdd(&g_done, 1u);
        if (done == (unsigned)(B * G - 1)) {     // last block: all sums final
            double s0 = atomicAdd(&g_sums[0], 0.0);
            double s1 = atomicAdd(&g_sums[1], 0.0);
            out[0] = (float)(s0 * (0.5 / 128.0));    // ALPHA / (B*G)
            out[1] = (float)(s1 * (0.5 / 6400.0));   // (1-ALPHA) / (B*G*TOPK)
        }
    }
}

// ------------------------------ launch -----------------------------------
extern "C" void kernel_launch(void* const* d_in, const int* in_sizes, int n_in,
                              void* d_out, int out_size) {
    const float4* br     = (const float4*)d_in[0];   // box_regression (B,A,4)
    const float*  logits = (const float*) d_in[1];   // cls_logits (B,A,C)
    const float4* anc    = (const float4*)d_in[2];   // anchors (A,4)
    const float4* tbx    = (const float4*)d_in[3];   // targets_boxes (B,G,4)
    const int*    lab    = (const int*)   d_in[4];   // labels (B,G)
    float* out = (float*)d_out;

    kI<<<1, 128>>>();
    kAN<<<KA_BLOCKS + KN_BLOCKS, 256>>>(br, anc, tbx, (const float4*)logits);
    kT<<<B * G, 256>>>();
    kD<<<KD_SCAN_BLOCKS + KD_SP_BLOCKS, 256>>>(br, anc, tbx, lab, logits);
    kS<<<B * G, 256>>>(br, anc, tbx, lab, logits, out);
}